// round 16
// baseline (speedup 1.0000x reference)
#include <cuda_runtime.h>
#include <cuda_fp16.h>
#include <math_constants.h>
#include <cstdint>

#define TOKENS  8192
#define HIDDEN  6144
#define EXPERTS 768
#define TOPK    12
#define NCAND   13
#define RSCALE  2.5f
#define TAU     1e-4f

// ---------------- GEMM config (R13 frozen) ----------------
#define BM 128
#define BN 128
#define BK 64
#define NSTAGES (HIDDEN / BK)    // 96
#define RING 3
#define TILE_B  (BM * 128)
#define STAGE_B (2 * TILE_B)
#define GEMM_SMEM (RING * STAGE_B)  // 98304
#define NX 6                      // n-tiles per m-block

#define NA4 (TOKENS * HIDDEN / 4)
#define NW4 (EXPERTS * HIDDEN / 4)
#define CVT_BLOCKS ((NA4 + NW4) / (256 * 4))   // 13440 exact

__device__ __half g_Ah[(size_t)TOKENS * HIDDEN];
__device__ __half g_Wh[(size_t)EXPERTS * HIDDEN];
__device__ float  g_logits[(size_t)TOKENS * EXPERTS];

// ---------------- helpers ----------------
__device__ __forceinline__ uint32_t smem_u32(const void* p) {
    uint32_t a;
    asm("{ .reg .u64 t; cvta.to.shared.u64 t, %1; cvt.u32.u64 %0, t; }" : "=r"(a) : "l"(p));
    return a;
}
__device__ __forceinline__ uint2 f4_to_h4(float4 v) {
    __half2 p0 = __floats2half2_rn(v.x, v.y);
    __half2 p1 = __floats2half2_rn(v.z, v.w);
    return make_uint2(*(uint32_t*)&p0, *(uint32_t*)&p1);
}
__device__ __forceinline__ void cp16(uint32_t dst, const void* src) {
    asm volatile("cp.async.cg.shared.global [%0], [%1], 16;" :: "r"(dst), "l"(src) : "memory");
}
#define CP_COMMIT() asm volatile("cp.async.commit_group;" ::: "memory")
#define CP_WAIT1()  asm volatile("cp.async.wait_group 1;" ::: "memory")

__device__ __forceinline__ void ldm_x4(uint32_t* r, uint32_t addr) {
    asm volatile("ldmatrix.sync.aligned.m8n8.x4.shared.b16 {%0,%1,%2,%3}, [%4];"
                 : "=r"(r[0]), "=r"(r[1]), "=r"(r[2]), "=r"(r[3]) : "r"(addr));
}
__device__ __forceinline__ void mma16(float* c, const uint32_t* a, const uint32_t* b) {
    asm volatile(
        "mma.sync.aligned.m16n8k16.row.col.f32.f16.f16.f32 "
        "{%0,%1,%2,%3}, {%4,%5,%6,%7}, {%8,%9}, {%0,%1,%2,%3};"
        : "+f"(c[0]), "+f"(c[1]), "+f"(c[2]), "+f"(c[3])
        : "r"(a[0]), "r"(a[1]), "r"(a[2]), "r"(a[3]), "r"(b[0]), "r"(b[1]));
}
__device__ __forceinline__ uint32_t swz(int row, int ch) {
    return (uint32_t)(row * 128 + ((ch ^ (row & 7)) << 4));
}
__device__ __forceinline__ uint32_t fkey(float x) {
    uint32_t u = __float_as_uint(x);
    return (u & 0x80000000u) ? ~u : (u | 0x80000000u);
}
__device__ __forceinline__ float fval(uint32_t k) {
    uint32_t u = (k & 0x80000000u) ? (k & 0x7FFFFFFFu) : ~k;
    return __uint_as_float(u);
}

// ---------------------------------------------------------------------------
// Merged fp32->fp16 conversion (R13, at DRAM floor).
// ---------------------------------------------------------------------------
__global__ __launch_bounds__(256)
void cvt_all_kernel(const float4* __restrict__ inA, const float4* __restrict__ inW,
                    uint2* __restrict__ outA, uint2* __restrict__ outW) {
    const int base   = blockIdx.x * blockDim.x + threadIdx.x;
    const int stride = gridDim.x * blockDim.x;
    #pragma unroll
    for (int k = 0; k < 4; k++) {
        const int i = base + k * stride;
        if (i < NA4) outA[i] = f4_to_h4(inA[i]);
        else         outW[i - NA4] = f4_to_h4(inW[i - NA4]);
    }
}

// ---------------------------------------------------------------------------
// GEMM tile body (R13 exact, parameterized by tile index).
// ---------------------------------------------------------------------------
__device__ void gemm_tile(int tile, char* smem) {
    const uint32_t smbase = smem_u32(smem);
    const int tid  = threadIdx.x;
    const int wid  = tid >> 5;
    const int lane = tid & 31;
    const int m0 = (tile / NX) * BM;
    const int n0 = (tile % NX) * BN;

    const int wm = wid & 1;
    const int wn = wid >> 1;
    const int wrow = tid >> 3;
    const int wc   = tid & 7;

    const __half* Abase = g_Ah + (size_t)m0 * HIDDEN;
    const __half* Bbase = g_Wh + (size_t)n0 * HIDDEN;

    float acc[4][4][4];
    #pragma unroll
    for (int mi = 0; mi < 4; mi++)
        #pragma unroll
        for (int ni = 0; ni < 4; ni++)
            #pragma unroll
            for (int j = 0; j < 4; j++) acc[mi][ni][j] = 0.0f;

    auto issue = [&](int s) {
        const uint32_t slot = smbase + (s % RING) * STAGE_B;
        const __half* ga = Abase + s * BK;
        const __half* gb = Bbase + s * BK;
        #pragma unroll
        for (int i = 0; i < 4; i++) {
            const int row = wrow + 32 * i;
            const uint32_t so = swz(row, wc);
            cp16(slot + so,          ga + (size_t)row * HIDDEN + wc * 8);
            cp16(slot + TILE_B + so, gb + (size_t)row * HIDDEN + wc * 8);
        }
    };

    issue(0); CP_COMMIT();
    issue(1); CP_COMMIT();

    const int a_row = wm * 64 + (lane & 7) + ((lane >> 3) & 1) * 8;
    const int a_chl = (lane >> 4) & 1;
    const int b_row = wn * 32 + (lane & 7) + ((lane >> 4) & 1) * 8;
    const int b_chl = (lane >> 3) & 1;

    for (int s = 0; s < NSTAGES; s++) {
        CP_WAIT1();
        __syncthreads();
        if (s + 2 < NSTAGES) issue(s + 2);
        CP_COMMIT();

        const uint32_t sA = smbase + (s % RING) * STAGE_B;
        const uint32_t sB = sA + TILE_B;

        #pragma unroll
        for (int w = 0; w < 4; w++) {
            uint32_t af[4][4], bf[2][4];
            #pragma unroll
            for (int mi = 0; mi < 4; mi++)
                ldm_x4(af[mi], sA + swz(a_row + mi * 16, w * 2 + a_chl));
            #pragma unroll
            for (int p = 0; p < 2; p++)
                ldm_x4(bf[p], sB + swz(b_row + p * 16, w * 2 + b_chl));
            #pragma unroll
            for (int mi = 0; mi < 4; mi++) {
                mma16(acc[mi][0], af[mi], &bf[0][0]);
                mma16(acc[mi][1], af[mi], &bf[0][2]);
                mma16(acc[mi][2], af[mi], &bf[1][0]);
                mma16(acc[mi][3], af[mi], &bf[1][2]);
            }
        }
    }

    #pragma unroll
    for (int mi = 0; mi < 4; mi++) {
        const int row = m0 + wm * 64 + mi * 16 + (lane >> 2);
        #pragma unroll
        for (int ni = 0; ni < 4; ni++) {
            const int col = n0 + wn * 32 + ni * 8 + (lane & 3) * 2;
            *(float2*)(g_logits + (size_t)row * EXPERTS + col)       = make_float2(acc[mi][ni][0], acc[mi][ni][1]);
            *(float2*)(g_logits + (size_t)(row + 8) * EXPERTS + col) = make_float2(acc[mi][ni][2], acc[mi][ni][3]);
        }
    }
}

// ---------------------------------------------------------------------------
// Topk body (R12 proven version, 8 warps/block; one token per warp).
// ---------------------------------------------------------------------------
__device__ void topk_block(int token, const float* __restrict__ A,
                           const float* __restrict__ W,
                           const float* __restrict__ bias,
                           float* __restrict__ out) {
    const int lane  = threadIdx.x & 31;
    const int wslot = threadIdx.x >> 5;    // 0..7

    __shared__ float s_cb[8][NCAND];
    __shared__ float s_cs[8][NCAND];
    __shared__ int   s_ce[8][NCAND];

    const float* row = g_logits + (size_t)token * EXPERTS;

    float b[24];
    #pragma unroll
    for (int j = 0; j < 24; j++) b[j] = row[j * 32 + lane];

    float m = b[0];
    #pragma unroll
    for (int j = 1; j < 24; j++) m = fmaxf(m, b[j]);
    #pragma unroll
    for (int off = 16; off; off >>= 1) m = fmaxf(m, __shfl_xor_sync(0xffffffffu, m, off));
    float ssum = 0.0f;
    #pragma unroll
    for (int j = 0; j < 24; j++) { b[j] = expf(b[j] - m); ssum += b[j]; }
    #pragma unroll
    for (int off = 16; off; off >>= 1) ssum += __shfl_xor_sync(0xffffffffu, ssum, off);
    const float inv = 1.0f / ssum;
    #pragma unroll
    for (int j = 0; j < 24; j++) b[j] = fmaf(b[j], inv, __ldg(&bias[j * 32 + lane]));

    for (int sel = 0; sel < NCAND; sel++) {
        float t12[12];
        #pragma unroll
        for (int j = 0; j < 12; j++) t12[j] = fmaxf(b[2 * j], b[2 * j + 1]);
        float t6[6];
        #pragma unroll
        for (int j = 0; j < 6; j++) t6[j] = fmaxf(t12[2 * j], t12[2 * j + 1]);
        const float v = fmaxf(fmaxf(fmaxf(t6[0], t6[1]), fmaxf(t6[2], t6[3])), fmaxf(t6[4], t6[5]));

        const uint32_t gk = __reduce_max_sync(0xffffffffu, fkey(v));
        const float vg = fval(gk);

        uint32_t msk = 0;
        #pragma unroll
        for (int j = 0; j < 24; j++) msk |= (b[j] == vg) ? (1u << j) : 0u;
        const uint32_t cand = msk ? (uint32_t)((__ffs(msk) - 1) * 32 + lane) : 0xFFFFFFFFu;
        const uint32_t idx = __reduce_min_sync(0xffffffffu, cand);

        if ((idx & 31u) == (uint32_t)lane) {
            const int jw = idx >> 5;
            #pragma unroll
            for (int j = 0; j < 24; j++) if (j == jw) b[j] = -CUDART_INF_F;
        }
        if (lane == 0) {
            s_cb[wslot][sel] = vg;
            s_cs[wslot][sel] = vg - __ldg(&bias[idx]);
            s_ce[wslot][sel] = (int)idx;
        }
    }
    __syncwarp();

    unsigned fmask = 0;
    #pragma unroll
    for (int r = 0; r < NCAND - 1; r++)
        if (s_cb[wslot][r] - s_cb[wslot][r + 1] < TAU) fmask |= (3u << r);

    const float* x = A + (size_t)token * HIDDEN;
    while (fmask) {
        const int r = __ffs(fmask) - 1;
        fmask &= fmask - 1;
        const int e = s_ce[wslot][r];
        const float* w = W + (size_t)e * HIDDEN;
        float p = 0.0f;
        #pragma unroll 8
        for (int jj = lane; jj < HIDDEN; jj += 32)
            p = fmaf(x[jj], w[jj], p);
        #pragma unroll
        for (int off = 16; off; off >>= 1)
            p += __shfl_xor_sync(0xffffffffu, p, off);
        if (lane == 0) {
            const float sn = expf(p - m) * inv;
            s_cs[wslot][r] = sn;
            s_cb[wslot][r] = sn + __ldg(&bias[e]);
        }
    }
    __syncwarp();

    if (lane < NCAND) {
        const float mv = s_cb[wslot][lane];
        const int   me = s_ce[wslot][lane];
        int rank = 0;
        #pragma unroll
        for (int j = 0; j < NCAND; j++) {
            const float jv = s_cb[wslot][j];
            const int   je = s_ce[wslot][j];
            if (jv > mv || (jv == mv && je < me)) rank++;
        }
        if (rank < TOPK) {
            out[(size_t)token * TOPK + rank]                         = (float)me;
            out[(size_t)TOKENS * TOPK + (size_t)token * TOPK + rank] = s_cs[wslot][lane] * RSCALE;
        }
    }
}

// ---------------------------------------------------------------------------
// Unified heterogeneous kernel: blocks [0, n_tiles) run GEMM tiles
// (tile_base + bid); remaining blocks run topk for 8 tokens each starting
// at tok_base. 2 blocks/SM (regs capped at 128, smem 98KB dynamic).
// ---------------------------------------------------------------------------
__global__ __launch_bounds__(256, 2)
void uni_kernel(int tile_base, int n_tiles, int tok_base,
                const float* __restrict__ A, const float* __restrict__ W,
                const float* __restrict__ bias, float* __restrict__ out) {
    extern __shared__ char smem[];
    const int bid = blockIdx.x;
    if (bid < n_tiles) {
        gemm_tile(tile_base + bid, smem);
    } else {
        const int token = tok_base + (bid - n_tiles) * 8 + (threadIdx.x >> 5);
        topk_block(token, A, W, bias, out);
    }
}

extern "C" void kernel_launch(void* const* d_in, const int* in_sizes, int n_in,
                              void* d_out, int out_size) {
    const float* A    = (const float*)d_in[0];
    const float* W    = (const float*)d_in[1];
    const float* bias = (const float*)d_in[2];
    float* out = (float*)d_out;

    __half* dAh = nullptr; __half* dWh = nullptr;
    cudaGetSymbolAddress((void**)&dAh, g_Ah);
    cudaGetSymbolAddress((void**)&dWh, g_Wh);

    cvt_all_kernel<<<CVT_BLOCKS, 256>>>((const float4*)A, (const float4*)W,
                                        (uint2*)dAh, (uint2*)dWh);

    cudaFuncSetAttribute(uni_kernel, cudaFuncAttributeMaxDynamicSharedMemorySize, GEMM_SMEM);

    // L1: tiles [0,148)  -> completes m-blocks 0..23 (tokens [0,3072))
    uni_kernel<<<148, 256, GEMM_SMEM>>>(0, 148, 0, A, W, bias, out);
    // L2: tiles [148,296) (completes m-blocks 24..48 -> tokens [3072,6272))
    //     + topk tokens [0,3072) = 384 blocks
    uni_kernel<<<148 + 384, 256, GEMM_SMEM>>>(148, 148, 0, A, W, bias, out);
    // L3: tiles [296,384) (completes all) + topk tokens [3072,6272) = 400 blocks
    uni_kernel<<<88 + 400, 256, GEMM_SMEM>>>(296, 88, 3072, A, W, bias, out);
    // L4: topk tokens [6272,8192) = 240 blocks
    uni_kernel<<<240, 256, GEMM_SMEM>>>(0, 0, 6272, A, W, bias, out);
}

// round 17
// speedup vs baseline: 1.4245x; 1.4245x over previous
#include <cuda_runtime.h>
#include <cuda_fp16.h>
#include <math_constants.h>
#include <cstdint>

#define TOKENS  8192
#define HIDDEN  6144
#define EXPERTS 768
#define TOPK    12
#define NCAND   13
#define RSCALE  2.5f
#define TAU     1e-4f

// ---------------- GEMM config (R13 frozen) ----------------
#define BM 128
#define BN 128
#define BK 64
#define NSTAGES (HIDDEN / BK)    // 96
#define RING 3
#define TILE_B  (BM * 128)
#define STAGE_B (2 * TILE_B)
#define GEMM_SMEM (RING * STAGE_B)  // 98304
#define NX 6                        // n-tiles per m-block
#define NMB (TOKENS / BM)           // 64 m-blocks

#define NA4 (TOKENS * HIDDEN / 4)
#define NW4 (EXPERTS * HIDDEN / 4)
#define CVT_BLOCKS ((NA4 + NW4) / (256 * 4))   // 13440 exact

__device__ __half g_Ah[(size_t)TOKENS * HIDDEN];
__device__ __half g_Wh[(size_t)EXPERTS * HIDDEN];
__device__ float  g_logits[(size_t)TOKENS * EXPERTS];
__device__ int    g_cnt[NMB];                    // per-m-block tile completion

// ---------------- helpers ----------------
__device__ __forceinline__ uint32_t smem_u32(const void* p) {
    uint32_t a;
    asm("{ .reg .u64 t; cvta.to.shared.u64 t, %1; cvt.u32.u64 %0, t; }" : "=r"(a) : "l"(p));
    return a;
}
__device__ __forceinline__ uint2 f4_to_h4(float4 v) {
    __half2 p0 = __floats2half2_rn(v.x, v.y);
    __half2 p1 = __floats2half2_rn(v.z, v.w);
    return make_uint2(*(uint32_t*)&p0, *(uint32_t*)&p1);
}
__device__ __forceinline__ void cp16(uint32_t dst, const void* src) {
    asm volatile("cp.async.cg.shared.global [%0], [%1], 16;" :: "r"(dst), "l"(src) : "memory");
}
#define CP_COMMIT() asm volatile("cp.async.commit_group;" ::: "memory")
#define CP_WAIT1()  asm volatile("cp.async.wait_group 1;" ::: "memory")

__device__ __forceinline__ void ldm_x4(uint32_t* r, uint32_t addr) {
    asm volatile("ldmatrix.sync.aligned.m8n8.x4.shared.b16 {%0,%1,%2,%3}, [%4];"
                 : "=r"(r[0]), "=r"(r[1]), "=r"(r[2]), "=r"(r[3]) : "r"(addr));
}
__device__ __forceinline__ void mma16(float* c, const uint32_t* a, const uint32_t* b) {
    asm volatile(
        "mma.sync.aligned.m16n8k16.row.col.f32.f16.f16.f32 "
        "{%0,%1,%2,%3}, {%4,%5,%6,%7}, {%8,%9}, {%0,%1,%2,%3};"
        : "+f"(c[0]), "+f"(c[1]), "+f"(c[2]), "+f"(c[3])
        : "r"(a[0]), "r"(a[1]), "r"(a[2]), "r"(a[3]), "r"(b[0]), "r"(b[1]));
}
__device__ __forceinline__ uint32_t swz(int row, int ch) {
    return (uint32_t)(row * 128 + ((ch ^ (row & 7)) << 4));
}
__device__ __forceinline__ uint32_t fkey(float x) {
    uint32_t u = __float_as_uint(x);
    return (u & 0x80000000u) ? ~u : (u | 0x80000000u);
}
__device__ __forceinline__ float fval(uint32_t k) {
    uint32_t u = (k & 0x80000000u) ? (k & 0x7FFFFFFFu) : ~k;
    return __uint_as_float(u);
}

// ---------------------------------------------------------------------------
// Merged fp32->fp16 conversion; block 0 also zeroes the m-block counters.
// ---------------------------------------------------------------------------
__global__ __launch_bounds__(256)
void cvt_all_kernel(const float4* __restrict__ inA, const float4* __restrict__ inW,
                    uint2* __restrict__ outA, uint2* __restrict__ outW) {
    if (blockIdx.x == 0 && threadIdx.x < NMB) g_cnt[threadIdx.x] = 0;
    const int base   = blockIdx.x * blockDim.x + threadIdx.x;
    const int stride = gridDim.x * blockDim.x;
    #pragma unroll
    for (int k = 0; k < 4; k++) {
        const int i = base + k * stride;
        if (i < NA4) outA[i] = f4_to_h4(inA[i]);
        else         outW[i - NA4] = f4_to_h4(inW[i - NA4]);
    }
}

// ---------------------------------------------------------------------------
// fp16 GEMM (R13 exact) + completion counter + PDL trigger.
// ---------------------------------------------------------------------------
__global__ __launch_bounds__(256, 2)
void router_gemm_cp() {
    extern __shared__ char smem[];
    const uint32_t smbase = smem_u32(smem);

    const int tid  = threadIdx.x;
    const int wid  = tid >> 5;
    const int lane = tid & 31;
    const int m0 = blockIdx.y * BM;
    const int n0 = blockIdx.x * BN;

    const int wm = wid & 1;
    const int wn = wid >> 1;
    const int wrow = tid >> 3;
    const int wc   = tid & 7;

    const __half* Abase = g_Ah + (size_t)m0 * HIDDEN;
    const __half* Bbase = g_Wh + (size_t)n0 * HIDDEN;

    float acc[4][4][4];
    #pragma unroll
    for (int mi = 0; mi < 4; mi++)
        #pragma unroll
        for (int ni = 0; ni < 4; ni++)
            #pragma unroll
            for (int j = 0; j < 4; j++) acc[mi][ni][j] = 0.0f;

    auto issue = [&](int s) {
        const uint32_t slot = smbase + (s % RING) * STAGE_B;
        const __half* ga = Abase + s * BK;
        const __half* gb = Bbase + s * BK;
        #pragma unroll
        for (int i = 0; i < 4; i++) {
            const int row = wrow + 32 * i;
            const uint32_t so = swz(row, wc);
            cp16(slot + so,          ga + (size_t)row * HIDDEN + wc * 8);
            cp16(slot + TILE_B + so, gb + (size_t)row * HIDDEN + wc * 8);
        }
    };

    issue(0); CP_COMMIT();
    issue(1); CP_COMMIT();

#if defined(CUDART_VERSION) && (CUDART_VERSION >= 11080)
    cudaTriggerProgrammaticLaunchCompletion();   // secondary may dispatch once ALL CTAs reach here
#endif

    const int a_row = wm * 64 + (lane & 7) + ((lane >> 3) & 1) * 8;
    const int a_chl = (lane >> 4) & 1;
    const int b_row = wn * 32 + (lane & 7) + ((lane >> 4) & 1) * 8;
    const int b_chl = (lane >> 3) & 1;

    for (int s = 0; s < NSTAGES; s++) {
        CP_WAIT1();
        __syncthreads();
        if (s + 2 < NSTAGES) issue(s + 2);
        CP_COMMIT();

        const uint32_t sA = smbase + (s % RING) * STAGE_B;
        const uint32_t sB = sA + TILE_B;

        #pragma unroll
        for (int w = 0; w < 4; w++) {
            uint32_t af[4][4], bf[2][4];
            #pragma unroll
            for (int mi = 0; mi < 4; mi++)
                ldm_x4(af[mi], sA + swz(a_row + mi * 16, w * 2 + a_chl));
            #pragma unroll
            for (int p = 0; p < 2; p++)
                ldm_x4(bf[p], sB + swz(b_row + p * 16, w * 2 + b_chl));
            #pragma unroll
            for (int mi = 0; mi < 4; mi++) {
                mma16(acc[mi][0], af[mi], &bf[0][0]);
                mma16(acc[mi][1], af[mi], &bf[0][2]);
                mma16(acc[mi][2], af[mi], &bf[1][0]);
                mma16(acc[mi][3], af[mi], &bf[1][2]);
            }
        }
    }

    #pragma unroll
    for (int mi = 0; mi < 4; mi++) {
        const int row = m0 + wm * 64 + mi * 16 + (lane >> 2);
        #pragma unroll
        for (int ni = 0; ni < 4; ni++) {
            const int col = n0 + wn * 32 + ni * 8 + (lane & 3) * 2;
            *(float2*)(g_logits + (size_t)row * EXPERTS + col)       = make_float2(acc[mi][ni][0], acc[mi][ni][1]);
            *(float2*)(g_logits + (size_t)(row + 8) * EXPERTS + col) = make_float2(acc[mi][ni][2], acc[mi][ni][3]);
        }
    }

    // publish: all stores visible at GPU scope, then count this tile
    __threadfence();
    __syncthreads();
    if (tid == 0) atomicAdd(&g_cnt[blockIdx.y], 1);
}

// ---------------------------------------------------------------------------
// Topk (R12/R13 exact) + per-m-block spin gate. 4 warps/block, 4 tokens/block.
// ---------------------------------------------------------------------------
__global__ __launch_bounds__(128, 8)
void topk_warp(const float* __restrict__ A, const float* __restrict__ W,
               const float* __restrict__ bias, float* __restrict__ out) {
    const int lane  = threadIdx.x & 31;
    const int wslot = threadIdx.x >> 5;
    const int token = blockIdx.x * 4 + wslot;
    const int mb    = blockIdx.x >> 5;            // (bid*4)/128

    // wait for this m-block's 6 tiles (passes instantly when not overlapped)
    if (threadIdx.x == 0) {
        volatile int* c = &g_cnt[mb];
        while (*c < NX) __nanosleep(256);
    }
    __syncthreads();
    __threadfence();

    const float* row = g_logits + (size_t)token * EXPERTS;

    __shared__ float s_cb[4][NCAND];
    __shared__ float s_cs[4][NCAND];
    __shared__ int   s_ce[4][NCAND];

    float b[24];
    #pragma unroll
    for (int j = 0; j < 24; j++) b[j] = __ldcg(&row[j * 32 + lane]);  // L2-coherent

    float m = b[0];
    #pragma unroll
    for (int j = 1; j < 24; j++) m = fmaxf(m, b[j]);
    #pragma unroll
    for (int off = 16; off; off >>= 1) m = fmaxf(m, __shfl_xor_sync(0xffffffffu, m, off));
    float ssum = 0.0f;
    #pragma unroll
    for (int j = 0; j < 24; j++) { b[j] = expf(b[j] - m); ssum += b[j]; }
    #pragma unroll
    for (int off = 16; off; off >>= 1) ssum += __shfl_xor_sync(0xffffffffu, ssum, off);
    const float inv = 1.0f / ssum;
    #pragma unroll
    for (int j = 0; j < 24; j++) b[j] = fmaf(b[j], inv, __ldg(&bias[j * 32 + lane]));

    for (int sel = 0; sel < NCAND; sel++) {
        float t12[12];
        #pragma unroll
        for (int j = 0; j < 12; j++) t12[j] = fmaxf(b[2 * j], b[2 * j + 1]);
        float t6[6];
        #pragma unroll
        for (int j = 0; j < 6; j++) t6[j] = fmaxf(t12[2 * j], t12[2 * j + 1]);
        const float v = fmaxf(fmaxf(fmaxf(t6[0], t6[1]), fmaxf(t6[2], t6[3])), fmaxf(t6[4], t6[5]));

        const uint32_t gk = __reduce_max_sync(0xffffffffu, fkey(v));
        const float vg = fval(gk);

        uint32_t msk = 0;
        #pragma unroll
        for (int j = 0; j < 24; j++) msk |= (b[j] == vg) ? (1u << j) : 0u;
        const uint32_t cand = msk ? (uint32_t)((__ffs(msk) - 1) * 32 + lane) : 0xFFFFFFFFu;
        const uint32_t idx = __reduce_min_sync(0xffffffffu, cand);

        if ((idx & 31u) == (uint32_t)lane) {
            const int jw = idx >> 5;
            #pragma unroll
            for (int j = 0; j < 24; j++) if (j == jw) b[j] = -CUDART_INF_F;
        }
        if (lane == 0) {
            s_cb[wslot][sel] = vg;
            s_cs[wslot][sel] = vg - __ldg(&bias[idx]);
            s_ce[wslot][sel] = (int)idx;
        }
    }
    __syncwarp();

    unsigned fmask = 0;
    #pragma unroll
    for (int r = 0; r < NCAND - 1; r++)
        if (s_cb[wslot][r] - s_cb[wslot][r + 1] < TAU) fmask |= (3u << r);

    const float* x = A + (size_t)token * HIDDEN;
    while (fmask) {
        const int r = __ffs(fmask) - 1;
        fmask &= fmask - 1;
        const int e = s_ce[wslot][r];
        const float* w = W + (size_t)e * HIDDEN;
        float p = 0.0f;
        #pragma unroll 8
        for (int jj = lane; jj < HIDDEN; jj += 32)
            p = fmaf(x[jj], w[jj], p);
        #pragma unroll
        for (int off = 16; off; off >>= 1)
            p += __shfl_xor_sync(0xffffffffu, p, off);
        if (lane == 0) {
            const float sn = expf(p - m) * inv;
            s_cs[wslot][r] = sn;
            s_cb[wslot][r] = sn + __ldg(&bias[e]);
        }
    }
    __syncwarp();

    if (lane < NCAND) {
        const float mv = s_cb[wslot][lane];
        const int   me = s_ce[wslot][lane];
        int rank = 0;
        #pragma unroll
        for (int j = 0; j < NCAND; j++) {
            const float jv = s_cb[wslot][j];
            const int   je = s_ce[wslot][j];
            if (jv > mv || (jv == mv && je < me)) rank++;
        }
        if (rank < TOPK) {
            out[(size_t)token * TOPK + rank]                         = (float)me;
            out[(size_t)TOKENS * TOPK + (size_t)token * TOPK + rank] = s_cs[wslot][lane] * RSCALE;
        }
    }
}

extern "C" void kernel_launch(void* const* d_in, const int* in_sizes, int n_in,
                              void* d_out, int out_size) {
    const float* A    = (const float*)d_in[0];
    const float* W    = (const float*)d_in[1];
    const float* bias = (const float*)d_in[2];
    float* out = (float*)d_out;

    __half* dAh = nullptr; __half* dWh = nullptr;
    cudaGetSymbolAddress((void**)&dAh, g_Ah);
    cudaGetSymbolAddress((void**)&dWh, g_Wh);

    cvt_all_kernel<<<CVT_BLOCKS, 256>>>((const float4*)A, (const float4*)W,
                                        (uint2*)dAh, (uint2*)dWh);

    cudaFuncSetAttribute(router_gemm_cp, cudaFuncAttributeMaxDynamicSharedMemorySize, GEMM_SMEM);
    dim3 grid(EXPERTS / BN, TOKENS / BM);   // (6, 64)
    router_gemm_cp<<<grid, 256, GEMM_SMEM>>>();

    // topk with PDL: may dispatch once all GEMM CTAs have started; gated by counters
    cudaLaunchConfig_t cfg = {};
    cfg.gridDim  = dim3(TOKENS / 4, 1, 1);
    cfg.blockDim = dim3(128, 1, 1);
    cfg.dynamicSmemBytes = 0;
    cudaLaunchAttribute attrs[1];
    attrs[0].id = cudaLaunchAttributeProgrammaticStreamSerialization;
    attrs[0].val.programmaticStreamSerializationAllowed = 1;
    cfg.attrs = attrs;
    cfg.numAttrs = 1;
    cudaError_t err = cudaLaunchKernelEx(&cfg, topk_warp, A, W, bias, out);
    if (err != cudaSuccess) {
        // fallback: plain launch (counters already satisfied -> spins pass instantly)
        topk_warp<<<TOKENS / 4, 128>>>(A, W, bias, out);
    }
}